// round 11
// baseline (speedup 1.0000x reference)
#include <cuda_runtime.h>
#include <cuda_fp16.h>
#include <math.h>

// Problem constants
#define SQ   2048
#define NB   2
#define EMB  1024
#define NH   16
#define HD   64
#define MTOT (SQ * NB)          // 4096
#define SCALE 0.125f
#define LOG2E 1.44269504088896f

// ---------------- fp16 scratch (allocation-free: __device__ globals) -------
__device__ __half g_xh [(size_t)MTOT * EMB];        // query fp16, m-major
__device__ __half g_w1h[(size_t)3 * EMB * EMB];     // in_proj_weight fp16
__device__ __half g_w2h[(size_t)EMB * EMB];         // out_w fp16
__device__ __half g_qh [(size_t)NB * NH * SQ * HD]; // (b,h,s,d), pre-scaled by SCALE*LOG2E
__device__ __half g_kh [(size_t)NB * NH * SQ * HD]; // (b,h,s,d)
__device__ __half g_vth[(size_t)NB * NH * HD * SQ]; // (b,h,d,s)  TRANSPOSED
__device__ __half g_ctxh[(size_t)NB * NH * SQ * HD];// (b,h,s,d)

// ---------------- helpers --------------------------------------------------
__device__ __forceinline__ unsigned smem_u32p(const void* p) {
    return (unsigned)__cvta_generic_to_shared(p);
}
__device__ __forceinline__ void cpa16(unsigned dst, const void* src) {
    asm volatile("cp.async.cg.shared.global [%0], [%1], 16;\n" :: "r"(dst), "l"(src));
}
__device__ __forceinline__ void cp_commit() { asm volatile("cp.async.commit_group;\n"); }
__device__ __forceinline__ void cp_wait0()  { asm volatile("cp.async.wait_group 0;\n" ::: "memory"); }

__device__ __forceinline__ void mma16816(float* c, const unsigned* a, const unsigned* b) {
    asm volatile(
        "mma.sync.aligned.m16n8k16.row.col.f32.f16.f16.f32 "
        "{%0,%1,%2,%3},{%4,%5,%6,%7},{%8,%9},{%0,%1,%2,%3};\n"
        : "+f"(c[0]), "+f"(c[1]), "+f"(c[2]), "+f"(c[3])
        : "r"(a[0]), "r"(a[1]), "r"(a[2]), "r"(a[3]), "r"(b[0]), "r"(b[1]));
}
__device__ __forceinline__ void ldsmx4(unsigned* r, const __half* p) {
    unsigned addr = smem_u32p(p);
    asm volatile("ldmatrix.sync.aligned.m8n8.x4.shared.b16 {%0,%1,%2,%3}, [%4];\n"
        : "=r"(r[0]), "=r"(r[1]), "=r"(r[2]), "=r"(r[3]) : "r"(addr));
}
__device__ __forceinline__ void ldsmx4a(unsigned* r, unsigned addr) {
    asm volatile("ldmatrix.sync.aligned.m8n8.x4.shared.b16 {%0,%1,%2,%3}, [%4];\n"
        : "=r"(r[0]), "=r"(r[1]), "=r"(r[2]), "=r"(r[3]) : "r"(addr));
}

// ---------------- fp32 -> fp16 convert (one fused launch) ------------------
#define N4_X  (MTOT * EMB / 4)
#define N4_W1 (3 * EMB * EMB / 4)
#define N4_W2 (EMB * EMB / 4)
#define N4_ALL (N4_X + N4_W1 + N4_W2)

__global__ void convert_all(const float4* __restrict__ x,
                            const float4* __restrict__ w1,
                            const float4* __restrict__ w2)
{
    int i = blockIdx.x * blockDim.x + threadIdx.x;
    const float4* src;
    __half2* dst;
    int j;
    if (i < N4_X)                  { src = x;  dst = (__half2*)g_xh;  j = i; }
    else if (i < N4_X + N4_W1)     { src = w1; dst = (__half2*)g_w1h; j = i - N4_X; }
    else if (i < N4_ALL)           { src = w2; dst = (__half2*)g_w2h; j = i - N4_X - N4_W1; }
    else return;
    float4 v = src[j];
    dst[2 * j]     = __floats2half2_rn(v.x, v.y);
    dst[2 * j + 1] = __floats2half2_rn(v.z, v.w);
}

// ---------------- GEMM: C[m,n] = sum_k A[m,k] * W[n,k] ---------------------
// 128x128x64 tile, 8 warps (4x2), warp tile 32x64, mma m16n8k16.
// 2-stage cp.async; 128B swizzled rows (chunk ^ (row&7)); ldmatrix frags.
// Epilogues vectorized: q/k half2, out float2, V via smem transpose.
#define BM 128
#define BN 128
#define BK 64
#define TILE_B (BM * BK * 2)              // 16 KB per operand tile
#define GSMEM (1024 + 4 * TILE_B)         // align slack + 2 stages x (A+W)
#define VCT 130                           // V-transpose smem col stride (halves)

template<int MODE>
__global__ __launch_bounds__(256)
void gemm_h(const float* __restrict__ bias, float* __restrict__ outp)
{
    extern __shared__ char dsm[];
    unsigned base = (smem_u32p(dsm) + 1023u) & ~1023u;

    const __half* A = (MODE == 0) ? g_xh  : g_ctxh;
    const __half* W = (MODE == 0) ? g_w1h : g_w2h;

    int tid  = threadIdx.x;
    int bm   = blockIdx.y, bn = blockIdx.x;
    int warp = tid >> 5, lane = tid & 31;
    int wm = warp & 3, wn = warp >> 2;

    float c[2][8][4];
    #pragma unroll
    for (int mt = 0; mt < 2; mt++)
        #pragma unroll
        for (int nt = 0; nt < 8; nt++)
            #pragma unroll
            for (int i = 0; i < 4; i++) c[mt][nt][i] = 0.f;

    auto stage = [&](int t, int buf) {
        int k0 = t * BK;
        unsigned ab = base + buf * TILE_B;
        unsigned wb = base + 2 * TILE_B + buf * TILE_B;
        #pragma unroll
        for (int j = 0; j < 4; j++) {
            int i = tid + j * 256;           // 0..1023
            int r = i >> 3, cc = i & 7;      // row, 16B chunk
            unsigned soff = r * 128 + ((cc ^ (r & 7)) * 16);
            const __half* asrc;
            if (MODE == 0) {
                asrc = A + (size_t)(bm * BM + r) * EMB + k0 + cc * 8;
            } else {
                int m = bm * BM + r;
                int s = m >> 1, b = m & 1;
                int kg = k0 + cc * 8;
                asrc = A + (((size_t)(b * NH + (kg >> 6)) * SQ + s) * HD + (kg & 63));
            }
            cpa16(ab + soff, asrc);
            cpa16(wb + soff, W + (size_t)(bn * BN + r) * EMB + k0 + cc * 8);
        }
        cp_commit();
    };

    const int NKT = EMB / BK;   // 16
    stage(0, 0);
    for (int t = 0; t < NKT; t++) {
        cp_wait0();
        __syncthreads();
        if (t + 1 < NKT) stage(t + 1, (t + 1) & 1);
        int buf = t & 1;
        unsigned ab = base + buf * TILE_B;
        unsigned wb = base + 2 * TILE_B + buf * TILE_B;

        #pragma unroll
        for (int ks = 0; ks < 4; ks++) {
            unsigned afr[2][4], bfr[8][2];
            int cc = 2 * ks + (lane >> 4);
            #pragma unroll
            for (int mt = 0; mt < 2; mt++) {
                int r = wm * 32 + mt * 16 + (lane & 15);
                int pc = cc ^ (r & 7);
                ldsmx4a(afr[mt], ab + r * 128 + pc * 16);
            }
            #pragma unroll
            for (int np = 0; np < 4; np++) {
                int n = wn * 64 + np * 16 + (lane & 15);
                int pc = cc ^ (n & 7);
                unsigned rr[4];
                ldsmx4a(rr, wb + n * 128 + pc * 16);
                bfr[2 * np][0]     = rr[0]; bfr[2 * np][1]     = rr[2];
                bfr[2 * np + 1][0] = rr[1]; bfr[2 * np + 1][1] = rr[3];
            }
            #pragma unroll
            for (int mt = 0; mt < 2; mt++)
                #pragma unroll
                for (int nt = 0; nt < 8; nt++)
                    mma16816(c[mt][nt], afr[mt], bfr[nt]);
        }
    }

    // ---------------- epilogue ----------------
    int g = lane >> 2, tig = lane & 3;
    int sec = (MODE == 0) ? ((bn * BN) >> 10) : 1;   // uniform per CTA (128 | 1024)

    if (MODE == 0 && sec == 2) {
        // V block: transpose through smem, then coalesced stores along s.
        __syncthreads();                      // mainloop smem reads done
        __half* ct = (__half*)dsm;            // 128 cols x VCT halves = 33,280 B
        #pragma unroll
        for (int mt = 0; mt < 2; mt++) {
            #pragma unroll
            for (int nt = 0; nt < 8; nt++) {
                #pragma unroll
                for (int i = 0; i < 4; i++) {
                    int rowL = wm * 32 + mt * 16 + g + ((i >= 2) ? 8 : 0);
                    int colL = wn * 64 + nt * 8 + 2 * tig + (i & 1);
                    int col = bn * BN + colL;
                    ct[colL * VCT + rowL] = __float2half(c[mt][nt][i] + __ldg(&bias[col]));
                }
            }
        }
        __syncthreads();
        // thread -> (col, s-half). 32 contiguous s per store target, both b.
        int colL = tid >> 1, sh = tid & 1;
        int col = bn * BN + colL;
        int r = col & 1023;
        int h = r >> 6, d = r & 63;
        const unsigned* src = (const unsigned*)(ct + colL * VCT);  // 4B-aligned (VCT even)
        unsigned w0[16], w1[16];
        #pragma unroll
        for (int tt = 0; tt < 16; tt++) {
            unsigned ua = src[sh * 32 + 2 * tt];       // halves: (b0,b1) for s=...
            unsigned ub = src[sh * 32 + 2 * tt + 1];
            w0[tt] = __byte_perm(ua, ub, 0x5410);      // b=0 halves packed
            w1[tt] = __byte_perm(ua, ub, 0x7632);      // b=1 halves packed
        }
        int s0 = bm * 64 + sh * 32;
        __half* d0 = g_vth + ((size_t)(0 * NH + h) * HD + d) * SQ + s0;
        __half* d1 = g_vth + ((size_t)(1 * NH + h) * HD + d) * SQ + s0;
        #pragma unroll
        for (int q4 = 0; q4 < 4; q4++) {
            *(uint4*)(d0 + q4 * 8) = *(uint4*)&w0[q4 * 4];
            *(uint4*)(d1 + q4 * 8) = *(uint4*)&w1[q4 * 4];
        }
    } else {
        #pragma unroll
        for (int mt = 0; mt < 2; mt++) {
            #pragma unroll
            for (int nt = 0; nt < 8; nt++) {
                int colL = wn * 64 + nt * 8 + 2 * tig;
                int col = bn * BN + colL;
                float b0 = __ldg(&bias[col]), b1 = __ldg(&bias[col + 1]);
                #pragma unroll
                for (int half = 0; half < 2; half++) {   // i pair (0,1) / (2,3)
                    int row = bm * BM + wm * 32 + mt * 16 + g + half * 8;
                    float v0 = c[mt][nt][2 * half]     + b0;
                    float v1 = c[mt][nt][2 * half + 1] + b1;
                    if (MODE == 0) {
                        int rr = col & 1023;
                        int h = rr >> 6, d = rr & 63;    // d even
                        int s = row >> 1, b = row & 1;
                        if (sec == 0) {
                            __half2 h2 = __floats2half2_rn(v0 * (SCALE * LOG2E),
                                                           v1 * (SCALE * LOG2E));
                            *(__half2*)&g_qh[((size_t)(b * NH + h) * SQ + s) * HD + d] = h2;
                        } else {
                            __half2 h2 = __floats2half2_rn(v0, v1);
                            *(__half2*)&g_kh[((size_t)(b * NH + h) * SQ + s) * HD + d] = h2;
                        }
                    } else {
                        float2 f2 = make_float2(v0, v1);
                        *(float2*)&outp[(size_t)row * EMB + col] = f2;
                    }
                }
            }
        }
    }
}

// ---------------- Flash attention, fp16 HMMA, exp2-domain softmax ----------
// CTA: 128 query rows of one (b,h); 8 warps x 16 rows. K/V tiles of 64,
// double-buffered cp.async, swizzled 128B rows, ldmatrix fragments.
// Logits pre-scaled by log2(e): p = exp2(s - m). Softmax invariant.
#define QT 128

__global__ __launch_bounds__(256, 2)
void flash_h()
{
    __shared__ __align__(16) __half Qs[QT * HD];       // 16 KB
    __shared__ __align__(16) __half Ks[2][64 * HD];    // 16 KB
    __shared__ __align__(16) __half Vt[2][64 * HD];    // 16 KB  (total 48 KB)

    int bh = blockIdx.y;
    int q0 = blockIdx.x * QT;
    int tid = threadIdx.x, warp = tid >> 5, lane = tid & 31;
    int g = lane >> 2, tig = lane & 3;

    const __half* qbase = g_qh + ((size_t)bh * SQ + q0) * HD;
    const __half* kbase = g_kh + (size_t)bh * SQ * HD;
    const __half* vbase = g_vth + (size_t)bh * HD * SQ;

    auto stageKV = [&](int buf, int kt) {
        #pragma unroll
        for (int j = 0; j < 2; j++) {
            int i = tid + j * 256;          // 0..511
            int r = i >> 3, cc = i & 7;
            int pc = cc ^ (r & 7);
            cpa16(smem_u32p(&Ks[buf][r * HD + pc * 8]),
                  kbase + (size_t)(kt + r) * HD + cc * 8);
            cpa16(smem_u32p(&Vt[buf][r * HD + pc * 8]),
                  vbase + (size_t)r * SQ + kt + cc * 8);
        }
        cp_commit();
    };

    // stage Q tile (128x64) + first K/V
    #pragma unroll
    for (int j = 0; j < 4; j++) {
        int i = tid + j * 256;              // 0..1023
        int r = i >> 3, cc = i & 7;
        int pc = cc ^ (r & 7);
        cpa16(smem_u32p(&Qs[r * HD + pc * 8]), qbase + (size_t)r * HD + cc * 8);
    }
    stageKV(0, 0);
    cp_wait0();
    __syncthreads();

    unsigned qf[4][4];
    #pragma unroll
    for (int ks = 0; ks < 4; ks++) {
        int r = warp * 16 + (lane & 15);
        int cc = 2 * ks + (lane >> 4);
        int pc = cc ^ (r & 7);
        ldsmx4(qf[ks], &Qs[r * HD + pc * 8]);
    }

    float o[8][4];
    #pragma unroll
    for (int nt = 0; nt < 8; nt++)
        #pragma unroll
        for (int i = 0; i < 4; i++) o[nt][i] = 0.f;
    float m0 = -1e30f, m1 = -1e30f, l0 = 0.f, l1 = 0.f;

    const int NT = SQ / 64;
    for (int it = 0; it < NT; it++) {
        if (it > 0) {
            cp_wait0();
            __syncthreads();
        }
        if (it + 1 < NT) stageKV((it + 1) & 1, (it + 1) * 64);
        int buf = it & 1;

        float s[8][4];
        #pragma unroll
        for (int nt = 0; nt < 8; nt++)
            #pragma unroll
            for (int i = 0; i < 4; i++) s[nt][i] = 0.f;
        #pragma unroll
        for (int ks = 0; ks < 4; ks++) {
            int cc = 2 * ks + (lane >> 4);
            #pragma unroll
            for (int np = 0; np < 4; np++) {
                int n = np * 16 + (lane & 15);
                int pc = cc ^ (n & 7);
                unsigned rr[4];
                ldsmx4(rr, &Ks[buf][n * HD + pc * 8]);
                unsigned bA[2] = {rr[0], rr[2]};
                unsigned bB[2] = {rr[1], rr[3]};
                mma16816(s[2 * np],     qf[ks], bA);
                mma16816(s[2 * np + 1], qf[ks], bB);
            }
        }

        float t0 = -1e30f, t1 = -1e30f;
        #pragma unroll
        for (int nt = 0; nt < 8; nt++) {
            t0 = fmaxf(t0, fmaxf(s[nt][0], s[nt][1]));
            t1 = fmaxf(t1, fmaxf(s[nt][2], s[nt][3]));
        }
        t0 = fmaxf(t0, __shfl_xor_sync(0xffffffffu, t0, 1));
        t0 = fmaxf(t0, __shfl_xor_sync(0xffffffffu, t0, 2));
        t1 = fmaxf(t1, __shfl_xor_sync(0xffffffffu, t1, 1));
        t1 = fmaxf(t1, __shfl_xor_sync(0xffffffffu, t1, 2));

        float nm0 = fmaxf(m0, t0), nm1 = fmaxf(m1, t1);
        float sc0 = exp2f(m0 - nm0), sc1 = exp2f(m1 - nm1);
        m0 = nm0; m1 = nm1;
        l0 *= sc0; l1 *= sc1;
        #pragma unroll
        for (int nt = 0; nt < 8; nt++) {
            o[nt][0] *= sc0; o[nt][1] *= sc0;
            o[nt][2] *= sc1; o[nt][3] *= sc1;
        }

        unsigned pf[4][4];
        float ps0 = 0.f, ps1 = 0.f;
        #pragma unroll
        for (int ks = 0; ks < 4; ks++) {
            int ta = 2 * ks, tb = 2 * ks + 1;
            __half2 h0 = __floats2half2_rn(exp2f(s[ta][0] - m0), exp2f(s[ta][1] - m0));
            __half2 h1 = __floats2half2_rn(exp2f(s[ta][2] - m1), exp2f(s[ta][3] - m1));
            __half2 h2 = __floats2half2_rn(exp2f(s[tb][0] - m0), exp2f(s[tb][1] - m0));
            __half2 h3 = __floats2half2_rn(exp2f(s[tb][2] - m1), exp2f(s[tb][3] - m1));
            pf[ks][0] = *(unsigned*)&h0;
            pf[ks][1] = *(unsigned*)&h1;
            pf[ks][2] = *(unsigned*)&h2;
            pf[ks][3] = *(unsigned*)&h3;
            float2 f;
            f = __half22float2(h0); ps0 += f.x + f.y;
            f = __half22float2(h2); ps0 += f.x + f.y;
            f = __half22float2(h1); ps1 += f.x + f.y;
            f = __half22float2(h3); ps1 += f.x + f.y;
        }
        ps0 += __shfl_xor_sync(0xffffffffu, ps0, 1);
        ps0 += __shfl_xor_sync(0xffffffffu, ps0, 2);
        ps1 += __shfl_xor_sync(0xffffffffu, ps1, 1);
        ps1 += __shfl_xor_sync(0xffffffffu, ps1, 2);
        l0 += ps0; l1 += ps1;

        #pragma unroll
        for (int ks = 0; ks < 4; ks++) {
            int cc = 2 * ks + (lane >> 4);
            #pragma unroll
            for (int np = 0; np < 4; np++) {
                int r = np * 16 + (lane & 15);
                int pc = cc ^ (r & 7);
                unsigned rr[4];
                ldsmx4(rr, &Vt[buf][r * HD + pc * 8]);
                unsigned bA[2] = {rr[0], rr[2]};
                unsigned bB[2] = {rr[1], rr[3]};
                mma16816(o[2 * np],     pf[ks], bA);
                mma16816(o[2 * np + 1], pf[ks], bB);
            }
        }
    }

    float inv0 = 1.f / l0, inv1 = 1.f / l1;
    int row0 = q0 + warp * 16 + g;
    __half* obase = g_ctxh + (size_t)bh * SQ * HD;
    #pragma unroll
    for (int nt = 0; nt < 8; nt++) {
        int colb = nt * 8 + 2 * tig;
        __half2 ha = __floats2half2_rn(o[nt][0] * inv0, o[nt][1] * inv0);
        __half2 hb = __floats2half2_rn(o[nt][2] * inv1, o[nt][3] * inv1);
        *(__half2*)&obase[(size_t)row0 * HD + colb] = ha;
        *(__half2*)&obase[(size_t)(row0 + 8) * HD + colb] = hb;
    }
}

// ---------------------------------------------------------------------------
extern "C" void kernel_launch(void* const* d_in, const int* in_sizes, int n_in,
                              void* d_out, int out_size)
{
    const float* query = (const float*)d_in[0];   // (S,B,E)
    const float* w_in  = (const float*)d_in[1];   // (3E,E)
    const float* b_in  = (const float*)d_in[2];   // (3E,)
    const float* w_out = (const float*)d_in[3];   // (E,E)
    const float* b_out = (const float*)d_in[4];   // (E,)
    float* out = (float*)d_out;                   // (S,B,E)

    static int attr_done = 0;
    if (!attr_done) {
        cudaFuncSetAttribute(gemm_h<0>, cudaFuncAttributeMaxDynamicSharedMemorySize, GSMEM);
        cudaFuncSetAttribute(gemm_h<1>, cudaFuncAttributeMaxDynamicSharedMemorySize, GSMEM);
        attr_done = 1;
    }

    convert_all<<<(N4_ALL + 255) / 256, 256>>>((const float4*)query,
                                               (const float4*)w_in,
                                               (const float4*)w_out);

    // QKV: M=4096, N=3072, K=1024
    gemm_h<0><<<dim3(3 * EMB / BN, MTOT / BM), 256, GSMEM>>>(b_in, nullptr);
    // Attention
    flash_h<<<dim3(SQ / QT, NB * NH), 256>>>();
    // Out proj: M=4096, N=1024, K=1024
    gemm_h<1><<<dim3(EMB / BN, MTOT / BM), 256, GSMEM>>>(b_out, out);
}

// round 12
// speedup vs baseline: 1.0644x; 1.0644x over previous
#include <cuda_runtime.h>
#include <cuda_fp16.h>
#include <math.h>

// Problem constants
#define SQ   2048
#define NB   2
#define EMB  1024
#define NH   16
#define HD   64
#define MTOT (SQ * NB)          // 4096
#define SCALE 0.125f
#define LOG2E 1.44269504088896f

// ---------------- fp16 scratch (allocation-free: __device__ globals) -------
__device__ __half g_xh [(size_t)MTOT * EMB];        // query fp16, m-major
__device__ __half g_w1h[(size_t)3 * EMB * EMB];     // in_proj_weight fp16
__device__ __half g_w2h[(size_t)EMB * EMB];         // out_w fp16
__device__ __half g_qh [(size_t)NB * NH * SQ * HD]; // (b,h,s,d), pre-scaled by SCALE*LOG2E
__device__ __half g_kh [(size_t)NB * NH * SQ * HD]; // (b,h,s,d)
__device__ __half g_vth[(size_t)NB * NH * HD * SQ]; // (b,h,d,s)  TRANSPOSED
__device__ __half g_ctxh[(size_t)MTOT * EMB];       // ctx, M-MAJOR [m][E] (e = h*64+d)

// ---------------- helpers --------------------------------------------------
__device__ __forceinline__ unsigned smem_u32p(const void* p) {
    return (unsigned)__cvta_generic_to_shared(p);
}
__device__ __forceinline__ void cpa16(unsigned dst, const void* src) {
    asm volatile("cp.async.cg.shared.global [%0], [%1], 16;\n" :: "r"(dst), "l"(src));
}
__device__ __forceinline__ void cp_commit() { asm volatile("cp.async.commit_group;\n"); }
__device__ __forceinline__ void cp_wait0()  { asm volatile("cp.async.wait_group 0;\n" ::: "memory"); }

__device__ __forceinline__ void mma16816(float* c, const unsigned* a, const unsigned* b) {
    asm volatile(
        "mma.sync.aligned.m16n8k16.row.col.f32.f16.f16.f32 "
        "{%0,%1,%2,%3},{%4,%5,%6,%7},{%8,%9},{%0,%1,%2,%3};\n"
        : "+f"(c[0]), "+f"(c[1]), "+f"(c[2]), "+f"(c[3])
        : "r"(a[0]), "r"(a[1]), "r"(a[2]), "r"(a[3]), "r"(b[0]), "r"(b[1]));
}
__device__ __forceinline__ void ldsmx4(unsigned* r, const __half* p) {
    unsigned addr = smem_u32p(p);
    asm volatile("ldmatrix.sync.aligned.m8n8.x4.shared.b16 {%0,%1,%2,%3}, [%4];\n"
        : "=r"(r[0]), "=r"(r[1]), "=r"(r[2]), "=r"(r[3]) : "r"(addr));
}
__device__ __forceinline__ void ldsmx4a(unsigned* r, unsigned addr) {
    asm volatile("ldmatrix.sync.aligned.m8n8.x4.shared.b16 {%0,%1,%2,%3}, [%4];\n"
        : "=r"(r[0]), "=r"(r[1]), "=r"(r[2]), "=r"(r[3]) : "r"(addr));
}

// ---------------- fp32 -> fp16 convert (one fused launch) ------------------
#define N4_X  (MTOT * EMB / 4)
#define N4_W1 (3 * EMB * EMB / 4)
#define N4_W2 (EMB * EMB / 4)
#define N4_ALL (N4_X + N4_W1 + N4_W2)

__global__ void convert_all(const float4* __restrict__ x,
                            const float4* __restrict__ w1,
                            const float4* __restrict__ w2)
{
    int i = blockIdx.x * blockDim.x + threadIdx.x;
    const float4* src;
    __half2* dst;
    int j;
    if (i < N4_X)                  { src = x;  dst = (__half2*)g_xh;  j = i; }
    else if (i < N4_X + N4_W1)     { src = w1; dst = (__half2*)g_w1h; j = i - N4_X; }
    else if (i < N4_ALL)           { src = w2; dst = (__half2*)g_w2h; j = i - N4_X - N4_W1; }
    else return;
    float4 v = src[j];
    dst[2 * j]     = __floats2half2_rn(v.x, v.y);
    dst[2 * j + 1] = __floats2half2_rn(v.z, v.w);
}

// ---------------- GEMM: C[m,n] = sum_k A[m,k] * W[n,k] ---------------------
// 128x128x64 tile, 8 warps (4x2), warp tile 32x64, mma m16n8k16.
// 2-stage cp.async; 128B swizzled rows (chunk ^ (row&7)); ldmatrix frags.
// A is m-major for BOTH modes (ctx is stored m-major by flash).
#define BM 128
#define BN 128
#define BK 64
#define TILE_B (BM * BK * 2)              // 16 KB per operand tile
#define GSMEM (1024 + 4 * TILE_B)         // align slack + 2 stages x (A+W)
#define VCT 130                           // V-transpose smem col stride (halves)

template<int MODE>
__global__ __launch_bounds__(256)
void gemm_h(const float* __restrict__ bias, float* __restrict__ outp)
{
    extern __shared__ char dsm[];
    unsigned base = (smem_u32p(dsm) + 1023u) & ~1023u;

    const __half* A = (MODE == 0) ? g_xh  : g_ctxh;
    const __half* W = (MODE == 0) ? g_w1h : g_w2h;

    int tid  = threadIdx.x;
    int bm   = blockIdx.y, bn = blockIdx.x;
    int warp = tid >> 5, lane = tid & 31;
    int wm = warp & 3, wn = warp >> 2;

    float c[2][8][4];
    #pragma unroll
    for (int mt = 0; mt < 2; mt++)
        #pragma unroll
        for (int nt = 0; nt < 8; nt++)
            #pragma unroll
            for (int i = 0; i < 4; i++) c[mt][nt][i] = 0.f;

    auto stage = [&](int t, int buf) {
        int k0 = t * BK;
        unsigned ab = base + buf * TILE_B;
        unsigned wb = base + 2 * TILE_B + buf * TILE_B;
        #pragma unroll
        for (int j = 0; j < 4; j++) {
            int i = tid + j * 256;           // 0..1023
            int r = i >> 3, cc = i & 7;      // row, 16B chunk
            unsigned soff = r * 128 + ((cc ^ (r & 7)) * 16);
            cpa16(ab + soff, A + (size_t)(bm * BM + r) * EMB + k0 + cc * 8);
            cpa16(wb + soff, W + (size_t)(bn * BN + r) * EMB + k0 + cc * 8);
        }
        cp_commit();
    };

    const int NKT = EMB / BK;   // 16
    stage(0, 0);
    for (int t = 0; t < NKT; t++) {
        cp_wait0();
        __syncthreads();
        if (t + 1 < NKT) stage(t + 1, (t + 1) & 1);
        int buf = t & 1;
        unsigned ab = base + buf * TILE_B;
        unsigned wb = base + 2 * TILE_B + buf * TILE_B;

        #pragma unroll
        for (int ks = 0; ks < 4; ks++) {
            unsigned afr[2][4], bfr[8][2];
            int cc = 2 * ks + (lane >> 4);
            #pragma unroll
            for (int mt = 0; mt < 2; mt++) {
                int r = wm * 32 + mt * 16 + (lane & 15);
                int pc = cc ^ (r & 7);
                ldsmx4a(afr[mt], ab + r * 128 + pc * 16);
            }
            #pragma unroll
            for (int np = 0; np < 4; np++) {
                int n = wn * 64 + np * 16 + (lane & 15);
                int pc = cc ^ (n & 7);
                unsigned rr[4];
                ldsmx4a(rr, wb + n * 128 + pc * 16);
                bfr[2 * np][0]     = rr[0]; bfr[2 * np][1]     = rr[2];
                bfr[2 * np + 1][0] = rr[1]; bfr[2 * np + 1][1] = rr[3];
            }
            #pragma unroll
            for (int mt = 0; mt < 2; mt++)
                #pragma unroll
                for (int nt = 0; nt < 8; nt++)
                    mma16816(c[mt][nt], afr[mt], bfr[nt]);
        }
    }

    // ---------------- epilogue ----------------
    int g = lane >> 2, tig = lane & 3;
    int sec = (MODE == 0) ? ((bn * BN) >> 10) : 1;   // uniform per CTA (128 | 1024)

    if (MODE == 0 && sec == 2) {
        // V block: transpose through smem, then coalesced stores along s.
        __syncthreads();                      // mainloop smem reads done
        __half* ct = (__half*)dsm;            // 128 cols x VCT halves = 33,280 B
        #pragma unroll
        for (int mt = 0; mt < 2; mt++) {
            #pragma unroll
            for (int nt = 0; nt < 8; nt++) {
                #pragma unroll
                for (int i = 0; i < 4; i++) {
                    int rowL = wm * 32 + mt * 16 + g + ((i >= 2) ? 8 : 0);
                    int colL = wn * 64 + nt * 8 + 2 * tig + (i & 1);
                    int col = bn * BN + colL;
                    ct[colL * VCT + rowL] = __float2half(c[mt][nt][i] + __ldg(&bias[col]));
                }
            }
        }
        __syncthreads();
        // thread -> (col, s-half). 32 contiguous s per store target, both b.
        int colL = tid >> 1, sh = tid & 1;
        int col = bn * BN + colL;
        int r = col & 1023;
        int h = r >> 6, d = r & 63;
        const unsigned* src = (const unsigned*)(ct + colL * VCT);  // 4B-aligned (VCT even)
        unsigned w0[16], w1[16];
        #pragma unroll
        for (int tt = 0; tt < 16; tt++) {
            unsigned ua = src[sh * 32 + 2 * tt];       // halves: (b0,b1) for s=...
            unsigned ub = src[sh * 32 + 2 * tt + 1];
            w0[tt] = __byte_perm(ua, ub, 0x5410);      // b=0 halves packed
            w1[tt] = __byte_perm(ua, ub, 0x7632);      // b=1 halves packed
        }
        int s0 = bm * 64 + sh * 32;
        __half* d0 = g_vth + ((size_t)(0 * NH + h) * HD + d) * SQ + s0;
        __half* d1 = g_vth + ((size_t)(1 * NH + h) * HD + d) * SQ + s0;
        #pragma unroll
        for (int q4 = 0; q4 < 4; q4++) {
            *(uint4*)(d0 + q4 * 8) = *(uint4*)&w0[q4 * 4];
            *(uint4*)(d1 + q4 * 8) = *(uint4*)&w1[q4 * 4];
        }
    } else {
        #pragma unroll
        for (int mt = 0; mt < 2; mt++) {
            #pragma unroll
            for (int nt = 0; nt < 8; nt++) {
                int colL = wn * 64 + nt * 8 + 2 * tig;
                int col = bn * BN + colL;
                float b0 = __ldg(&bias[col]), b1 = __ldg(&bias[col + 1]);
                #pragma unroll
                for (int half = 0; half < 2; half++) {   // i pair (0,1) / (2,3)
                    int row = bm * BM + wm * 32 + mt * 16 + g + half * 8;
                    float v0 = c[mt][nt][2 * half]     + b0;
                    float v1 = c[mt][nt][2 * half + 1] + b1;
                    if (MODE == 0) {
                        int rr = col & 1023;
                        int h = rr >> 6, d = rr & 63;    // d even
                        int s = row >> 1, b = row & 1;
                        if (sec == 0) {
                            __half2 h2 = __floats2half2_rn(v0 * (SCALE * LOG2E),
                                                           v1 * (SCALE * LOG2E));
                            *(__half2*)&g_qh[((size_t)(b * NH + h) * SQ + s) * HD + d] = h2;
                        } else {
                            __half2 h2 = __floats2half2_rn(v0, v1);
                            *(__half2*)&g_kh[((size_t)(b * NH + h) * SQ + s) * HD + d] = h2;
                        }
                    } else {
                        float2 f2 = make_float2(v0, v1);
                        *(float2*)&outp[(size_t)row * EMB + col] = f2;
                    }
                }
            }
        }
    }
}

// ---------------- Flash attention, fp16 HMMA, exp2-domain softmax ----------
// CTA: 64 query rows of one (b,h); 4 warps x 16 rows. K/V tiles of 64,
// double-buffered cp.async, swizzled 128B rows, ldmatrix fragments.
// ctx written M-MAJOR: ctx[(s*2+b)*EMB + h*64 + d].
__global__ __launch_bounds__(128, 4)
void flash_h()
{
    __shared__ __align__(16) __half Qs[64 * HD];
    __shared__ __align__(16) __half Ks[2][64 * HD];
    __shared__ __align__(16) __half Vt[2][64 * HD];

    int bh = blockIdx.y;
    int q0 = blockIdx.x * 64;
    int tid = threadIdx.x, warp = tid >> 5, lane = tid & 31;
    int g = lane >> 2, tig = lane & 3;
    int b = bh >> 4, h = bh & 15;        // NH = 16

    const __half* qbase = g_qh + ((size_t)bh * SQ + q0) * HD;
    const __half* kbase = g_kh + (size_t)bh * SQ * HD;
    const __half* vbase = g_vth + (size_t)bh * HD * SQ;

    auto stageKV = [&](int buf, int kt) {
        #pragma unroll
        for (int j = 0; j < 4; j++) {
            int i = tid + j * 128;
            int r = i >> 3, cc = i & 7;
            int pc = cc ^ (r & 7);
            cpa16(smem_u32p(&Ks[buf][r * HD + pc * 8]),
                  kbase + (size_t)(kt + r) * HD + cc * 8);
            cpa16(smem_u32p(&Vt[buf][r * HD + pc * 8]),
                  vbase + (size_t)r * SQ + kt + cc * 8);
        }
        cp_commit();
    };

    #pragma unroll
    for (int j = 0; j < 4; j++) {
        int i = tid + j * 128;
        int r = i >> 3, cc = i & 7;
        int pc = cc ^ (r & 7);
        cpa16(smem_u32p(&Qs[r * HD + pc * 8]), qbase + (size_t)r * HD + cc * 8);
    }
    stageKV(0, 0);
    cp_wait0();
    __syncthreads();

    unsigned qf[4][4];
    #pragma unroll
    for (int ks = 0; ks < 4; ks++) {
        int r = warp * 16 + (lane & 15);
        int cc = 2 * ks + (lane >> 4);
        int pc = cc ^ (r & 7);
        ldsmx4(qf[ks], &Qs[r * HD + pc * 8]);
    }

    float o[8][4];
    #pragma unroll
    for (int nt = 0; nt < 8; nt++)
        #pragma unroll
        for (int i = 0; i < 4; i++) o[nt][i] = 0.f;
    float m0 = -1e30f, m1 = -1e30f, l0 = 0.f, l1 = 0.f;

    const int NT = SQ / 64;
    for (int it = 0; it < NT; it++) {
        if (it > 0) {
            cp_wait0();
            __syncthreads();
        }
        if (it + 1 < NT) stageKV((it + 1) & 1, (it + 1) * 64);
        int buf = it & 1;

        float s[8][4];
        #pragma unroll
        for (int nt = 0; nt < 8; nt++)
            #pragma unroll
            for (int i = 0; i < 4; i++) s[nt][i] = 0.f;
        #pragma unroll
        for (int ks = 0; ks < 4; ks++) {
            int cc = 2 * ks + (lane >> 4);
            #pragma unroll
            for (int np = 0; np < 4; np++) {
                int n = np * 16 + (lane & 15);
                int pc = cc ^ (n & 7);
                unsigned rr[4];
                ldsmx4(rr, &Ks[buf][n * HD + pc * 8]);
                unsigned bA[2] = {rr[0], rr[2]};
                unsigned bB[2] = {rr[1], rr[3]};
                mma16816(s[2 * np],     qf[ks], bA);
                mma16816(s[2 * np + 1], qf[ks], bB);
            }
        }

        float t0 = -1e30f, t1 = -1e30f;
        #pragma unroll
        for (int nt = 0; nt < 8; nt++) {
            t0 = fmaxf(t0, fmaxf(s[nt][0], s[nt][1]));
            t1 = fmaxf(t1, fmaxf(s[nt][2], s[nt][3]));
        }
        t0 = fmaxf(t0, __shfl_xor_sync(0xffffffffu, t0, 1));
        t0 = fmaxf(t0, __shfl_xor_sync(0xffffffffu, t0, 2));
        t1 = fmaxf(t1, __shfl_xor_sync(0xffffffffu, t1, 1));
        t1 = fmaxf(t1, __shfl_xor_sync(0xffffffffu, t1, 2));

        float nm0 = fmaxf(m0, t0), nm1 = fmaxf(m1, t1);
        float sc0 = exp2f(m0 - nm0), sc1 = exp2f(m1 - nm1);
        m0 = nm0; m1 = nm1;
        l0 *= sc0; l1 *= sc1;
        #pragma unroll
        for (int nt = 0; nt < 8; nt++) {
            o[nt][0] *= sc0; o[nt][1] *= sc0;
            o[nt][2] *= sc1; o[nt][3] *= sc1;
        }

        unsigned pf[4][4];
        float ps0 = 0.f, ps1 = 0.f;
        #pragma unroll
        for (int ks = 0; ks < 4; ks++) {
            int ta = 2 * ks, tb = 2 * ks + 1;
            __half2 h0 = __floats2half2_rn(exp2f(s[ta][0] - m0), exp2f(s[ta][1] - m0));
            __half2 h1 = __floats2half2_rn(exp2f(s[ta][2] - m1), exp2f(s[ta][3] - m1));
            __half2 h2 = __floats2half2_rn(exp2f(s[tb][0] - m0), exp2f(s[tb][1] - m0));
            __half2 h3 = __floats2half2_rn(exp2f(s[tb][2] - m1), exp2f(s[tb][3] - m1));
            pf[ks][0] = *(unsigned*)&h0;
            pf[ks][1] = *(unsigned*)&h1;
            pf[ks][2] = *(unsigned*)&h2;
            pf[ks][3] = *(unsigned*)&h3;
            float2 f;
            f = __half22float2(h0); ps0 += f.x + f.y;
            f = __half22float2(h2); ps0 += f.x + f.y;
            f = __half22float2(h1); ps1 += f.x + f.y;
            f = __half22float2(h3); ps1 += f.x + f.y;
        }
        ps0 += __shfl_xor_sync(0xffffffffu, ps0, 1);
        ps0 += __shfl_xor_sync(0xffffffffu, ps0, 2);
        ps1 += __shfl_xor_sync(0xffffffffu, ps1, 1);
        ps1 += __shfl_xor_sync(0xffffffffu, ps1, 2);
        l0 += ps0; l1 += ps1;

        #pragma unroll
        for (int ks = 0; ks < 4; ks++) {
            int cc = 2 * ks + (lane >> 4);
            #pragma unroll
            for (int np = 0; np < 4; np++) {
                int r = np * 16 + (lane & 15);
                int pc = cc ^ (r & 7);
                unsigned rr[4];
                ldsmx4(rr, &Vt[buf][r * HD + pc * 8]);
                unsigned bA[2] = {rr[0], rr[2]};
                unsigned bB[2] = {rr[1], rr[3]};
                mma16816(o[2 * np],     pf[ks], bA);
                mma16816(o[2 * np + 1], pf[ks], bB);
            }
        }
    }

    // normalize + write ctx (fp16, M-MAJOR: [(s*2+b)][h*64+d])
    float inv0 = 1.f / l0, inv1 = 1.f / l1;
    int s_row = q0 + warp * 16 + g;
    __half* ob0 = g_ctxh + ((size_t)(s_row) * NB + b) * EMB + h * HD;
    __half* ob1 = g_ctxh + ((size_t)(s_row + 8) * NB + b) * EMB + h * HD;
    #pragma unroll
    for (int nt = 0; nt < 8; nt++) {
        int colb = nt * 8 + 2 * tig;
        __half2 ha = __floats2half2_rn(o[nt][0] * inv0, o[nt][1] * inv0);
        __half2 hb = __floats2half2_rn(o[nt][2] * inv1, o[nt][3] * inv1);
        *(__half2*)&ob0[colb] = ha;
        *(__half2*)&ob1[colb] = hb;
    }
}

// ---------------------------------------------------------------------------
extern "C" void kernel_launch(void* const* d_in, const int* in_sizes, int n_in,
                              void* d_out, int out_size)
{
    const float* query = (const float*)d_in[0];   // (S,B,E)
    const float* w_in  = (const float*)d_in[1];   // (3E,E)
    const float* b_in  = (const float*)d_in[2];   // (3E,)
    const float* w_out = (const float*)d_in[3];   // (E,E)
    const float* b_out = (const float*)d_in[4];   // (E,)
    float* out = (float*)d_out;                   // (S,B,E)

    static int attr_done = 0;
    if (!attr_done) {
        cudaFuncSetAttribute(gemm_h<0>, cudaFuncAttributeMaxDynamicSharedMemorySize, GSMEM);
        cudaFuncSetAttribute(gemm_h<1>, cudaFuncAttributeMaxDynamicSharedMemorySize, GSMEM);
        attr_done = 1;
    }

    convert_all<<<(N4_ALL + 255) / 256, 256>>>((const float4*)query,
                                               (const float4*)w_in,
                                               (const float4*)w_out);

    // QKV: M=4096, N=3072, K=1024
    gemm_h<0><<<dim3(3 * EMB / BN, MTOT / BM), 256, GSMEM>>>(b_in, nullptr);
    // Attention
    flash_h<<<dim3(SQ / 64, NB * NH), 128>>>();
    // Out proj: M=4096, N=1024, K=1024
    gemm_h<1><<<dim3(EMB / BN, MTOT / BM), 256, GSMEM>>>(b_out, out);
}